// round 8
// baseline (speedup 1.0000x reference)
#include <cuda_runtime.h>
#include <math.h>

#define N_POINTS 16384
#define N_PAIRS  65536

#define TILE     256
#define TGRID    (N_POINTS / TILE)               // 64
#define HEAVY_BLOCKS (TGRID * (TGRID + 1) / 2)   // 2080
#define PAIR_BLOCKS  64
#define NBLOCKS  (HEAVY_BLOCKS + PAIR_BLOCKS)    // 2144
#define NTHREADS 128
#define JP       (TILE / 2)                      // 128 j-pairs per tile

typedef unsigned long long u64;
typedef unsigned int u32;

// ---- device scratch (no allocation allowed) ----------------------------------
__device__ float g_part_p[HEAVY_BLOCKS];
__device__ float g_kld_p[PAIR_BLOCKS];
__device__ float g_pair_p[PAIR_BLOCKS];
__device__ float g_pij_p[PAIR_BLOCKS];
__device__ unsigned int g_ticket = 0;

// ---- packed f32x2 helpers -----------------------------------------------------
__device__ __forceinline__ u64 pack2(float lo, float hi) {
    u64 r; asm("mov.b64 %0, {%1, %2};" : "=l"(r) : "f"(lo), "f"(hi)); return r;
}
__device__ __forceinline__ void unpack2f(float& lo, float& hi, u64 v) {
    asm("mov.b64 {%0, %1}, %2;" : "=f"(lo), "=f"(hi) : "l"(v));
}
__device__ __forceinline__ u64 fma2(u64 a, u64 b, u64 c) {
    u64 d; asm("fma.rn.f32x2 %0, %1, %2, %3;" : "=l"(d) : "l"(a), "l"(b), "l"(c)); return d;
}
__device__ __forceinline__ u64 add2(u64 a, u64 b) {
    u64 d; asm("add.rn.f32x2 %0, %1, %2;" : "=l"(d) : "l"(a), "l"(b)); return d;
}

// ---- reductions (128 threads = 4 warps) ----------------------------------------
__device__ __forceinline__ float warp_reduce(float v) {
    #pragma unroll
    for (int o = 16; o > 0; o >>= 1) v += __shfl_xor_sync(0xffffffffu, v, o);
    return v;
}
__device__ __forceinline__ float block_reduce(float v, float* smem) {
    v = warp_reduce(v);
    int lane = threadIdx.x & 31, wid = threadIdx.x >> 5;
    if (lane == 0) smem[wid] = v;
    __syncthreads();
    v = (threadIdx.x < 4) ? smem[threadIdx.x] : 0.0f;
    if (wid == 0) {
        v += __shfl_xor_sync(0xffffffffu, v, 2);
        v += __shfl_xor_sync(0xffffffffu, v, 1);
    }
    return v;  // valid in thread 0
}

// ---- reparam helper: x = eps*exp(0.5*lv) + mu ----------------------------------
__device__ __forceinline__ float2 reparam_pt(const float* __restrict__ mu,
                                             const float* __restrict__ lv,
                                             const float* __restrict__ eps,
                                             int idx) {
    float2 m = ((const float2*)mu)[idx];
    float2 l = ((const float2*)lv)[idx];
    float2 e = ((const float2*)eps)[idx];
    float2 x;
    x.x = fmaf(e.x, __expf(0.5f * l.x), m.x);
    x.y = fmaf(e.y, __expf(0.5f * l.y), m.y);
    return x;
}

// ---- single fused kernel --------------------------------------------------------
__global__ __launch_bounds__(NTHREADS, 10)
void k_main(const float* __restrict__ pij,
            const int*   __restrict__ ii,
            const int*   __restrict__ jj,
            const float* __restrict__ mu,
            const float* __restrict__ lv,
            const float* __restrict__ epsf,
            const float* __restrict__ epsi,
            const float* __restrict__ epsj,
            float* __restrict__ out) {
    __shared__ __align__(16) ulonglong2 s_cxcy[JP];  // per j-pair: (cx01, cy01), c = -2x
    __shared__ __align__(16) u64        s_b[JP];     // per j-pair: (1+|xj|^2) x2
    __shared__ float  sred[4];
    __shared__ float  sred1[4];
    __shared__ double sdd[NTHREADS];
    __shared__ unsigned int s_last;

    const int bid = blockIdx.x;
    const int tid = threadIdx.x;

    if (bid < HEAVY_BLOCKS) {
        // -------- heavy path: upper-tri tile (a,b), 256x256 ----------------------
        int a = 0, rem = bid;
        while (rem >= TGRID - a) { rem -= TGRID - a; a++; }
        int b = a + rem;
        int i0 = a * TILE;
        int j0 = b * TILE;
        float wt = (a == b) ? 1.0f : 2.0f;

        // j-tile: thread t owns j-pair t = points (j0+2t, j0+2t+1)
        {
            int q = (j0 >> 1) + tid;    // float4 index (2 points per float4)
            float4 m = ((const float4*)mu)[q];
            float4 l = ((const float4*)lv)[q];
            float4 e = ((const float4*)epsf)[q];
            float x0x = fmaf(e.x, __expf(0.5f * l.x), m.x);
            float x0y = fmaf(e.y, __expf(0.5f * l.y), m.y);
            float x1x = fmaf(e.z, __expf(0.5f * l.z), m.z);
            float x1y = fmaf(e.w, __expf(0.5f * l.w), m.w);
            ulonglong2 cc;
            cc.x = pack2(-2.0f * x0x, -2.0f * x1x);
            cc.y = pack2(-2.0f * x0y, -2.0f * x1y);
            s_cxcy[tid] = cc;
            s_b[tid] = pack2(fmaf(x0x, x0x, fmaf(x0y, x0y, 1.0f)),
                             fmaf(x1x, x1x, fmaf(x1y, x1y, 1.0f)));
        }

        // two i-chains per thread (256 i per CTA)
        float2 xa = reparam_pt(mu, lv, epsf, i0 + tid);
        float2 xb = reparam_pt(mu, lv, epsf, i0 + NTHREADS + tid);
        u64 xax2 = pack2(xa.x, xa.x), xay2 = pack2(xa.y, xa.y);
        u64 xbx2 = pack2(xb.x, xb.x), xby2 = pack2(xb.y, xb.y);
        float haf = fmaf(xa.x, xa.x, xa.y * xa.y);   // |xi|^2
        float hbf = fmaf(xb.x, xb.x, xb.y * xb.y);
        u64 ha2 = pack2(haf, haf);
        u64 hb2 = pack2(hbf, hbf);
        const u64 TWO2 = pack2(2.0f, 2.0f);
        const u64 MAGIC2 = 0xFEF127EAFEF127EAull;
        u64 acc0 = 0ull, acc1 = 0ull;

        __syncthreads();

        // k=1 magic+Newton: per j-pair per i-chain: 5 fma-pipe + 2 alu ops
        #pragma unroll 8
        for (int p = 0; p < JP; p++) {
            ulonglong2 cc = s_cxcy[p];   // LDS.128
            u64 b2 = s_b[p];             // LDS.64
            // d = (1 + |xj|^2 + |xi|^2) - 2 xi.xj = 1 + dist^2 >= 1
            u64 da = fma2(cc.x, xax2, fma2(cc.y, xay2, add2(b2, ha2)));
            u64 ya = MAGIC2 - da;        // ~ -(1/da), sign bit set, no borrow
            u64 ta = fma2(da, ya, TWO2); // 2 - da*y
            acc0 = fma2(ya, ta, acc0);   // acc -= newton(1/da)

            u64 db = fma2(cc.x, xbx2, fma2(cc.y, xby2, add2(b2, hb2)));
            u64 yb = MAGIC2 - db;
            u64 tb = fma2(db, yb, TWO2);
            acc1 = fma2(yb, tb, acc1);
        }

        float a0l, a0h, a1l, a1h;
        unpack2f(a0l, a0h, acc0);
        unpack2f(a1l, a1h, acc1);
        // acc holds negated sums
        float sres = block_reduce(-((a0l + a0h) + (a1l + a1h)), sred);
        if (tid == 0) g_part_p[bid] = sres * wt;
    } else {
        // -------- pairs path + KLD slice -----------------------------------------
        int pb = bid - HEAVY_BLOCKS;
        float term = 0.0f, psum = 0.0f;
        int base = pb * 1024;
        #pragma unroll
        for (int r = 0; r < 8; r++) {
            int p = base + r * NTHREADS + tid;
            int ai = ii[p], bi = jj[p];
            float2 ma = ((const float2*)mu)[ai];
            float2 la = ((const float2*)lv)[ai];
            float2 ea = ((const float2*)epsi)[p];
            float2 mb = ((const float2*)mu)[bi];
            float2 lb = ((const float2*)lv)[bi];
            float2 eb = ((const float2*)epsj)[p];
            float xax = fmaf(ea.x, __expf(0.5f * la.x), ma.x);
            float xay = fmaf(ea.y, __expf(0.5f * la.y), ma.y);
            float xbx = fmaf(eb.x, __expf(0.5f * lb.x), mb.x);
            float xby = fmaf(eb.y, __expf(0.5f * lb.y), mb.y);
            float da = xax - xbx, db = xay - xby;
            float d2 = fmaf(da, da, db * db);
            float pv = pij[p];
            // pij*(log pij - log qij) = pij*(log pij + log(1+d2)) + pij*log(part)
            term += pv * (logf(pv) + log1pf(d2));
            psum += pv;
        }
        // KLD slice: 256 points per pair-block (64 * 256 = 16384)
        float kld = 0.0f;
        #pragma unroll
        for (int r = 0; r < 2; r++) {
            int idx = pb * 256 + r * NTHREADS + tid;
            float2 m = ((const float2*)mu)[idx];
            float2 l = ((const float2*)lv)[idx];
            kld += (1.0f + l.x - m.x * m.x - __expf(l.x))
                 + (1.0f + l.y - m.y * m.y - __expf(l.y));
        }
        float s0 = block_reduce(term, sred);
        __syncthreads();
        float s1 = block_reduce(psum, sred1);
        __syncthreads();
        float s2 = block_reduce(kld, sred);
        if (tid == 0) {
            g_pair_p[pb] = s0;
            g_pij_p[pb]  = s1;
            g_kld_p[pb]  = s2;
        }
    }

    // -------- fused final: last CTA reduces everything ----------------------------
    __threadfence();
    if (tid == 0) s_last = atomicAdd(&g_ticket, 1u);
    __syncthreads();
    if (s_last == NBLOCKS - 1) {
        __threadfence();
        double part = 0.0, kld = 0.0, pair = 0.0, pijs = 0.0;
        for (int t = tid; t < HEAVY_BLOCKS; t += NTHREADS) part += (double)g_part_p[t];
        if (tid < PAIR_BLOCKS) {
            kld  = (double)g_kld_p[tid];
            pair = (double)g_pair_p[tid];
            pijs = (double)g_pij_p[tid];
        }
        double vals[4] = {part, kld, pair, pijs};
        double res[4];
        #pragma unroll
        for (int k = 0; k < 4; k++) {
            sdd[tid] = vals[k];
            __syncthreads();
            for (int o = NTHREADS / 2; o > 0; o >>= 1) {
                if (tid < o) sdd[tid] += sdd[tid + o];
                __syncthreads();
            }
            res[k] = sdd[0];
            __syncthreads();
        }
        if (tid == 0) {
            double partv = res[0] - (double)N_POINTS;   // remove diagonal
            double loss = res[2] + res[3] * log(partv) + 1e-7 * (-0.5 * res[1]);
            out[0] = (float)loss;
            g_ticket = 0;   // reset for next graph replay
        }
    }
}

// -----------------------------------------------------------------------------
extern "C" void kernel_launch(void* const* d_in, const int* in_sizes, int n_in,
                              void* d_out, int out_size) {
    const float* pij      = (const float*)d_in[0];
    const int*   i_idx    = (const int*)  d_in[1];
    const int*   j_idx    = (const int*)  d_in[2];
    const float* mu_w     = (const float*)d_in[3];
    const float* lv_w     = (const float*)d_in[4];
    const float* eps_full = (const float*)d_in[5];
    const float* eps_i    = (const float*)d_in[6];
    const float* eps_j    = (const float*)d_in[7];
    float* out = (float*)d_out;

    k_main<<<NBLOCKS, NTHREADS>>>(pij, i_idx, j_idx, mu_w, lv_w,
                                  eps_full, eps_i, eps_j, out);
}